// round 2
// baseline (speedup 1.0000x reference)
#include <cuda_runtime.h>

// Problem constants (fixed by the dataset)
#define N_TOK   65536      // 16 * 4096 rows
#define DDIM    256        // embedding size
#define KCODE   1024       // num embeddings
#define DECAY   0.99f
#define OMD     0.01f      // 1 - DECAY
#define EPSV    1e-5f
#define VQ_COMMIT 0.25f

// ---- scratch (no allocs allowed) ----
__device__ float g_esum[KCODE * DDIM];   // k-major: [k][d]
__device__ float g_counts[KCODE];
__device__ float g_enorm[KCODE];
__device__ float g_Et[KCODE * DDIM];     // transposed codebook, k-major
__device__ float g_invcs[KCODE];
__device__ float g_loss;

// ---------------------------------------------------------------------------
// k0: build Et (k-major codebook), zero esum/counts/loss
// ---------------------------------------------------------------------------
__global__ void k0_prep(const float* __restrict__ E) {
    int stride = gridDim.x * blockDim.x;
    for (int i = blockIdx.x * blockDim.x + threadIdx.x; i < KCODE * DDIM; i += stride) {
        int k  = i >> 8;        // i / 256
        int dd = i & 255;       // i % 256
        g_Et[i]   = E[dd * KCODE + k];
        g_esum[i] = 0.0f;
        if (i < KCODE) g_counts[i] = 0.0f;
        if (i == 0)    g_loss = 0.0f;
    }
}

// ---------------------------------------------------------------------------
// k0b: enorm[k] = ||e_k||^2, one warp per k, coalesced reads of Et
// ---------------------------------------------------------------------------
__global__ void k0_enorm() {
    int gw   = (blockIdx.x * blockDim.x + threadIdx.x) >> 5;
    int lane = threadIdx.x & 31;
    if (gw >= KCODE) return;
    const float4* row = (const float4*)(g_Et + (size_t)gw * DDIM);
    float s = 0.f;
    float4 a = row[lane];
    s += a.x * a.x + a.y * a.y + a.z * a.z + a.w * a.w;
    float4 b = row[lane + 32];
    s += b.x * b.x + b.y * b.y + b.z * b.z + b.w * b.w;
    #pragma unroll
    for (int o = 16; o; o >>= 1) s += __shfl_xor_sync(0xffffffffu, s, o);
    if (lane == 0) g_enorm[gw] = s;
}

// ---------------------------------------------------------------------------
// k1: fused GEMM (z @ E) + per-row argmin + gather z_q + scatter embed_sum
//     + counts + vq-loss accumulation.
//     BM=128 rows/CTA, BN=128 codes/chunk, BK=16, 256 threads, 8x8 microtile.
// ---------------------------------------------------------------------------
#define BM 128
#define BN 128
#define BK 16

__global__ __launch_bounds__(256, 2)
void k1_main(const float* __restrict__ z, const float* __restrict__ E,
             float* __restrict__ out_zq) {
    __shared__ float As[BK][BM + 4];   // pad to 132 floats (16B-aligned rows)
    __shared__ float Bs[BK][BN];
    __shared__ float red_v[BM][17];
    __shared__ int   red_i[BM][17];
    __shared__ float s_bv[BM];
    __shared__ int   s_bi[BM];
    __shared__ float enorm_s[BN];

    const int tid = threadIdx.x;
    const int tx = tid & 15;
    const int ty = tid >> 4;
    const int row0 = blockIdx.x * BM;

    float best_v = 3.4e38f;
    int   best_i = 0;

    for (int kc = 0; kc < KCODE / BN; ++kc) {
        const int k0 = kc * BN;
        float acc[8][8];
        #pragma unroll
        for (int i = 0; i < 8; ++i)
            #pragma unroll
            for (int j = 0; j < 8; ++j) acc[i][j] = 0.f;

        for (int ds = 0; ds < DDIM / BK; ++ds) {
            const int d0 = ds * BK;
            __syncthreads();
            // load A tile (z), transpose into As[d][m]
            {
                int r  = tid >> 2;
                int c4 = tid & 3;
                #pragma unroll
                for (int it = 0; it < 2; ++it) {
                    int rr = r + it * 64;
                    float4 v = *(const float4*)(z + (size_t)(row0 + rr) * DDIM + d0 + c4 * 4);
                    As[c4 * 4 + 0][rr] = v.x;
                    As[c4 * 4 + 1][rr] = v.y;
                    As[c4 * 4 + 2][rr] = v.z;
                    As[c4 * 4 + 3][rr] = v.w;
                }
            }
            // load B tile (E), already [d][k] in global
            {
                int dd  = tid >> 5;
                int kk4 = tid & 31;
                #pragma unroll
                for (int it = 0; it < 2; ++it) {
                    int d = dd + it * 8;
                    float4 v = *(const float4*)(E + (size_t)(d0 + d) * KCODE + k0 + kk4 * 4);
                    *(float4*)&Bs[d][kk4 * 4] = v;
                }
            }
            if (ds == 0 && tid < BN) enorm_s[tid] = g_enorm[k0 + tid];
            __syncthreads();

            #pragma unroll
            for (int kk = 0; kk < BK; ++kk) {
                float a[8], b[8];
                *(float4*)(a)     = *(const float4*)&As[kk][ty * 8];
                *(float4*)(a + 4) = *(const float4*)&As[kk][ty * 8 + 4];
                *(float4*)(b)     = *(const float4*)&Bs[kk][tx * 8];
                *(float4*)(b + 4) = *(const float4*)&Bs[kk][tx * 8 + 4];
                #pragma unroll
                for (int i = 0; i < 8; ++i)
                    #pragma unroll
                    for (int j = 0; j < 8; ++j)
                        acc[i][j] += a[i] * b[j];
            }
        }

        // per-thread min over its 8 columns for each of its 8 rows
        #pragma unroll
        for (int i = 0; i < 8; ++i) {
            float bv = 3.4e38f;
            int   bi = 0;
            #pragma unroll
            for (int j = 0; j < 8; ++j) {
                float s = enorm_s[tx * 8 + j] - 2.0f * acc[i][j];
                if (s < bv) { bv = s; bi = k0 + tx * 8 + j; }
            }
            red_v[ty * 8 + i][tx] = bv;
            red_i[ty * 8 + i][tx] = bi;
        }
        __syncthreads();
        if (tid < BM) {
            #pragma unroll
            for (int t = 0; t < 16; ++t) {
                float v  = red_v[tid][t];
                int   ii = red_i[tid][t];
                if (v < best_v || (v == best_v && ii < best_i)) { best_v = v; best_i = ii; }
            }
        }
        // next chunk's first __syncthreads orders red reuse
    }

    if (tid < BM) { s_bv[tid] = best_v; s_bi[tid] = best_i; }
    __syncthreads();

    // epilogue: gather z_q, scatter embed_sum, counts, loss. 16 rows per warp.
    const int lane = tid & 31;
    const int wid  = tid >> 5;
    const float4* Et4 = (const float4*)g_Et;
    float lossacc = 0.f;
    for (int rr = 0; rr < 16; ++rr) {
        int r = wid * 16 + rr;
        int R = row0 + r;
        int k = s_bi[r];
        const float4* zrow = (const float4*)(z + (size_t)R * DDIM);
        float4*       orow = (float4*)(out_zq + (size_t)R * DDIM);
        float zsq = 0.f;
        #pragma unroll
        for (int it = 0; it < 2; ++it) {
            int c = lane + it * 32;
            float4 zv = zrow[c];
            zsq += zv.x * zv.x + zv.y * zv.y + zv.z * zv.z + zv.w * zv.w;
            float* es = g_esum + (size_t)k * DDIM + c * 4;
            atomicAdd(es + 0, zv.x);
            atomicAdd(es + 1, zv.y);
            atomicAdd(es + 2, zv.z);
            atomicAdd(es + 3, zv.w);
            orow[c] = Et4[(size_t)k * 64 + c];
        }
        #pragma unroll
        for (int o = 16; o; o >>= 1) zsq += __shfl_xor_sync(0xffffffffu, zsq, o);
        if (lane == 0) {
            lossacc += zsq + s_bv[r];
            atomicAdd(&g_counts[k], 1.0f);
        }
    }
    if (lane == 0) atomicAdd(&g_loss, lossacc);
}

// ---------------------------------------------------------------------------
// k2: cluster_size_new, n-reduction, inv_cs, loss finalize (1 CTA, 1024 thr)
// ---------------------------------------------------------------------------
__global__ void k2_stats(const float* __restrict__ cs_in, float* __restrict__ out,
                         long long cs_off, long long loss_off) {
    __shared__ float red[KCODE];
    int t = threadIdx.x;
    float csn = cs_in[t] * DECAY + OMD * g_counts[t];
    out[cs_off + t] = csn;
    red[t] = csn;
    __syncthreads();
    for (int s = 512; s; s >>= 1) {
        if (t < s) red[t] += red[t + s];
        __syncthreads();
    }
    float n  = red[0];
    float cs = (csn + EPSV) / (n + (float)KCODE * EPSV) * n;
    g_invcs[t] = 1.0f / cs;
    if (t == 0) out[loss_off] = VQ_COMMIT * g_loss / (float)((long long)N_TOK * DDIM);
}

// ---------------------------------------------------------------------------
// k3: embedding_mean_new + embedding_new (elementwise over d x K)
// ---------------------------------------------------------------------------
__global__ void k3_emb(const float* __restrict__ emean, float* __restrict__ out,
                       long long en_off, long long emn_off) {
    int i = blockIdx.x * blockDim.x + threadIdx.x;
    if (i >= KCODE * DDIM) return;
    int dd = i >> 10;   // i / 1024
    int k  = i & 1023;  // i % 1024
    float emn = emean[i] * DECAY + OMD * g_esum[(size_t)k * DDIM + dd];
    out[emn_off + i] = emn;
    out[en_off + i]  = emn * g_invcs[k];
}

// ---------------------------------------------------------------------------
extern "C" void kernel_launch(void* const* d_in, const int* in_sizes, int n_in,
                              void* d_out, int out_size) {
    const float* z  = (const float*)d_in[0];   // [16,4096,256]
    const float* E  = (const float*)d_in[1];   // [256,1024]
    const float* cs = (const float*)d_in[2];   // [1024]
    const float* em = (const float*)d_in[3];   // [256,1024]
    float* out = (float*)d_out;

    long long ND = in_sizes[0];                // 16777216
    long long DK = in_sizes[1];                // 262144
    long long K  = in_sizes[2];                // 1024
    long long loss_off = ND;
    long long en_off   = ND + 1;
    long long cs_off   = en_off + DK;
    long long emn_off  = cs_off + K;

    k0_prep<<<512, 256>>>(E);
    k0_enorm<<<128, 256>>>();
    k1_main<<<N_TOK / BM, 256>>>(z, E, out);
    k2_stats<<<1, 1024>>>(cs, out, cs_off, loss_off);
    k3_emb<<<(KCODE * DDIM + 255) / 256, 256>>>(em, out, en_off, emn_off);
}

// round 3
// speedup vs baseline: 1.0693x; 1.0693x over previous
#include <cuda_runtime.h>
#include <cstdint>

#define N_TOK   65536
#define DDIM    256
#define KCODE   1024
#define DECAY   0.99f
#define OMD     0.01f
#define EPSV    1e-5f
#define VQ_COMMIT 0.25f

// ---- scratch ----
__device__ float g_esum[KCODE * DDIM];   // k-major [k][d]
__device__ float g_counts[KCODE];
__device__ float g_enorm[KCODE];
__device__ float g_Et[KCODE * DDIM];     // k-major codebook
__device__ float g_invcs[KCODE];
__device__ float g_loss;

// ---------------------------------------------------------------------------
__global__ void k0_prep(const float* __restrict__ E) {
    int stride = gridDim.x * blockDim.x;
    for (int i = blockIdx.x * blockDim.x + threadIdx.x; i < KCODE * DDIM; i += stride) {
        int k  = i >> 8;
        int dd = i & 255;
        g_Et[i]   = E[dd * KCODE + k];
        g_esum[i] = 0.0f;
        if (i < KCODE) g_counts[i] = 0.0f;
        if (i == 0)    g_loss = 0.0f;
    }
}

__global__ void k0_enorm() {
    int gw   = (blockIdx.x * blockDim.x + threadIdx.x) >> 5;
    int lane = threadIdx.x & 31;
    if (gw >= KCODE) return;
    const float4* row = (const float4*)(g_Et + (size_t)gw * DDIM);
    float s = 0.f;
    float4 a = row[lane];
    s += a.x * a.x + a.y * a.y + a.z * a.z + a.w * a.w;
    float4 b = row[lane + 32];
    s += b.x * b.x + b.y * b.y + b.z * b.z + b.w * b.w;
    #pragma unroll
    for (int o = 16; o; o >>= 1) s += __shfl_xor_sync(0xffffffffu, s, o);
    if (lane == 0) g_enorm[gw] = s;
}

// ---------------------------------------------------------------------------
// k1: FFMA2-packed GEMM + argmin + fused epilogue.
// 256 threads, BM=128, BN=128 (8 chunks), BK=16.
// A preloaded transposed to smem once; B streamed via cp.async 4-buf ring.
// ---------------------------------------------------------------------------
#define BM 128
#define BN 128
#define BK 16
#define APITCH 132
#define NBUF 4
#define NDS (DDIM / BK)   // 16
#define SMEM_K1 (DDIM * APITCH * 4 + NBUF * BK * BN * 4)  // 135168 + 32768

#define FMA2(c,a,b) asm("fma.rn.f32x2 %0, %1, %2, %3;" : "=l"(c) : "l"(a), "l"(b), "l"(c))
#define PACKDUP(d,f) asm("mov.b64 %0, {%1, %1};" : "=l"(d) : "r"(__float_as_uint(f)))

__device__ __forceinline__ void cp16(uint32_t dst, const void* src) {
    asm volatile("cp.async.cg.shared.global [%0], [%1], 16;" :: "r"(dst), "l"(src));
}

__device__ __forceinline__ void cp_tile(const float* __restrict__ E, int k0, int ds,
                                        int buf, uint32_t bs_u32, int tid) {
    int f = tid * 8;           // 8 floats / thread (32B)
    int d = f >> 7;            // 0..15
    int c = f & 127;
    const float* src = E + (size_t)(ds * BK + d) * KCODE + k0 + c;
    uint32_t dst = bs_u32 + (uint32_t)(((buf * BK + d) * BN + c) * 4);
    cp16(dst, src);
    cp16(dst + 16, src + 4);
    asm volatile("cp.async.commit_group;");
}

__global__ __launch_bounds__(256)
void k1_main(const float* __restrict__ z, const float* __restrict__ E,
             float* __restrict__ out_zq) {
    extern __shared__ float smem[];
    float* As = smem;                          // [DDIM][APITCH]
    float* Bs = smem + DDIM * APITCH;          // [NBUF][BK][BN]
    uint32_t bs_u32 = (uint32_t)__cvta_generic_to_shared(Bs);

    const int tid  = threadIdx.x;
    const int lane = tid & 31;     // = tx: cols tx*4 .. tx*4+3
    const int ty   = tid >> 5;     // warp: rows ty*16 .. ty*16+15
    const int tx4  = lane * 4;
    const int ty16 = ty * 16;
    const int row0 = blockIdx.x * BM;

    float bv[16];
    int   bi[16];
    #pragma unroll
    for (int r = 0; r < 16; ++r) { bv[r] = 3.4e38f; bi[r] = 0; }

    for (int kc = 0; kc < KCODE / BN; ++kc) {
        const int k0 = kc * BN;
        // pipeline prologue: 2 B tiles in flight
        cp_tile(E, k0, 0, 0, bs_u32, tid);
        cp_tile(E, k0, 1, 1, bs_u32, tid);

        if (kc == 0) {
            // preload full A block (transposed) once; overlaps with B cp flight
            #pragma unroll 4
            for (int it = 0; it < 32; ++it) {
                int v  = tid + it * 256;       // float4 index
                int r  = v >> 6;
                int c4 = v & 63;
                float4 zv = *(const float4*)(z + (size_t)(row0 + r) * DDIM + c4 * 4);
                float* col = As + (size_t)(c4 * 4) * APITCH + r;
                col[0 * APITCH] = zv.x;
                col[1 * APITCH] = zv.y;
                col[2 * APITCH] = zv.z;
                col[3 * APITCH] = zv.w;
            }
        }

        unsigned long long acc[8][4];
        #pragma unroll
        for (int i = 0; i < 8; ++i)
            #pragma unroll
            for (int j = 0; j < 4; ++j) acc[i][j] = 0ull;

        for (int ds = 0; ds < NDS; ++ds) {
            if (ds + 2 < NDS) {
                cp_tile(E, k0, ds + 2, (ds + 2) & 3, bs_u32, tid);
                asm volatile("cp.async.wait_group 2;");
            } else if (ds + 1 < NDS) {
                asm volatile("cp.async.wait_group 1;");
            } else {
                asm volatile("cp.async.wait_group 0;");
            }
            __syncthreads();

            const int d0 = ds * BK;
            const float* BsBuf = Bs + (size_t)(ds & 3) * BK * BN;
            #pragma unroll
            for (int kk = 0; kk < BK; ++kk) {
                const float* arow = As + (size_t)(d0 + kk) * APITCH + ty16;
                ulonglong2 a01 = *(const ulonglong2*)(arow);
                ulonglong2 a23 = *(const ulonglong2*)(arow + 4);
                ulonglong2 a45 = *(const ulonglong2*)(arow + 8);
                ulonglong2 a67 = *(const ulonglong2*)(arow + 12);
                float4 bf = *(const float4*)(BsBuf + kk * BN + tx4);
                unsigned long long b0, b1, b2, b3;
                PACKDUP(b0, bf.x); PACKDUP(b1, bf.y);
                PACKDUP(b2, bf.z); PACKDUP(b3, bf.w);
                unsigned long long ap[8] = {a01.x, a01.y, a23.x, a23.y,
                                            a45.x, a45.y, a67.x, a67.y};
                #pragma unroll
                for (int ip = 0; ip < 8; ++ip) {
                    FMA2(acc[ip][0], ap[ip], b0);
                    FMA2(acc[ip][1], ap[ip], b1);
                    FMA2(acc[ip][2], ap[ip], b2);
                    FMA2(acc[ip][3], ap[ip], b3);
                }
            }
        }

        // per-lane argmin update (dist = ||e||^2 - 2*dot; ||z||^2 added later)
        float4 en = *(const float4*)(g_enorm + k0 + tx4);
        float enj[4] = {en.x, en.y, en.z, en.w};
        #pragma unroll
        for (int ip = 0; ip < 8; ++ip) {
            #pragma unroll
            for (int j = 0; j < 4; ++j) {
                unsigned long long p = acc[ip][j];
                float lo = __uint_as_float((unsigned)p);
                float hi = __uint_as_float((unsigned)(p >> 32));
                float slo = enj[j] - 2.0f * lo;
                float shi = enj[j] - 2.0f * hi;
                int col = k0 + tx4 + j;
                if (slo < bv[2 * ip])     { bv[2 * ip]     = slo; bi[2 * ip]     = col; }
                if (shi < bv[2 * ip + 1]) { bv[2 * ip + 1] = shi; bi[2 * ip + 1] = col; }
            }
        }
    }

    // final per-row butterfly reduction + fused epilogue (warp-private rows)
    float lossacc = 0.f;
    #pragma unroll
    for (int r = 0; r < 16; ++r) {
        float v = bv[r];
        int   i = bi[r];
        #pragma unroll
        for (int o = 16; o; o >>= 1) {
            float ov = __shfl_xor_sync(0xffffffffu, v, o);
            int   oi = __shfl_xor_sync(0xffffffffu, i, o);
            if (ov < v || (ov == v && oi < i)) { v = ov; i = oi; }
        }
        int R = row0 + ty16 + r;
        const float4* zrow = (const float4*)(z + (size_t)R * DDIM);
        float4*       orow = (float4*)(out_zq + (size_t)R * DDIM);
        const float4* et   = (const float4*)(g_Et + (size_t)i * DDIM);
        float zsq = 0.f;
        #pragma unroll
        for (int itc = 0; itc < 2; ++itc) {
            int c = lane + itc * 32;
            float4 zv = zrow[c];
            zsq += zv.x * zv.x + zv.y * zv.y + zv.z * zv.z + zv.w * zv.w;
            float* es = g_esum + (size_t)i * DDIM + c * 4;
            atomicAdd(es + 0, zv.x);
            atomicAdd(es + 1, zv.y);
            atomicAdd(es + 2, zv.z);
            atomicAdd(es + 3, zv.w);
            orow[c] = et[c];
        }
        #pragma unroll
        for (int o = 16; o; o >>= 1) zsq += __shfl_xor_sync(0xffffffffu, zsq, o);
        if (lane == 0) {
            lossacc += zsq + v;
            atomicAdd(&g_counts[i], 1.0f);
        }
    }
    if (lane == 0) atomicAdd(&g_loss, lossacc);
}

// ---------------------------------------------------------------------------
__global__ void k2_stats(const float* __restrict__ cs_in, float* __restrict__ out,
                         long long cs_off, long long loss_off) {
    __shared__ float red[KCODE];
    int t = threadIdx.x;
    float csn = cs_in[t] * DECAY + OMD * g_counts[t];
    out[cs_off + t] = csn;
    red[t] = csn;
    __syncthreads();
    for (int s = 512; s; s >>= 1) {
        if (t < s) red[t] += red[t + s];
        __syncthreads();
    }
    float n  = red[0];
    float cs = (csn + EPSV) / (n + (float)KCODE * EPSV) * n;
    g_invcs[t] = 1.0f / cs;
    if (t == 0) out[loss_off] = VQ_COMMIT * g_loss / (float)((long long)N_TOK * DDIM);
}

__global__ void k3_emb(const float* __restrict__ emean, float* __restrict__ out,
                       long long en_off, long long emn_off) {
    int i = blockIdx.x * blockDim.x + threadIdx.x;
    if (i >= KCODE * DDIM) return;
    int dd = i >> 10;
    int k  = i & 1023;
    float emn = emean[i] * DECAY + OMD * g_esum[(size_t)k * DDIM + dd];
    out[emn_off + i] = emn;
    out[en_off + i]  = emn * g_invcs[k];
}

// ---------------------------------------------------------------------------
extern "C" void kernel_launch(void* const* d_in, const int* in_sizes, int n_in,
                              void* d_out, int out_size) {
    const float* z  = (const float*)d_in[0];
    const float* E  = (const float*)d_in[1];
    const float* cs = (const float*)d_in[2];
    const float* em = (const float*)d_in[3];
    float* out = (float*)d_out;

    long long ND = in_sizes[0];
    long long DK = in_sizes[1];
    long long K  = in_sizes[2];
    long long loss_off = ND;
    long long en_off   = ND + 1;
    long long cs_off   = en_off + DK;
    long long emn_off  = cs_off + K;

    cudaFuncSetAttribute(k1_main, cudaFuncAttributeMaxDynamicSharedMemorySize, SMEM_K1);

    k0_prep<<<512, 256>>>(E);
    k0_enorm<<<128, 256>>>();
    k1_main<<<N_TOK / BM, 256, SMEM_K1>>>(z, E, out);
    k2_stats<<<1, 1024>>>(cs, out, cs_off, loss_off);
    k3_emb<<<(KCODE * DDIM + 255) / 256, 256>>>(em, out, en_off, emn_off);
}

// round 4
// speedup vs baseline: 1.7139x; 1.6028x over previous
#include <cuda_runtime.h>
#include <cstdint>

#define N_TOK   65536
#define DDIM    256
#define KCODE   1024
#define DECAY   0.99f
#define OMD     0.01f
#define EPSV    1e-5f
#define VQ_COMMIT 0.25f

// ---- scratch ----
__device__ float g_esum[KCODE * DDIM];   // k-major [k][d]
__device__ float g_counts[KCODE];
__device__ float g_enorm[KCODE];
__device__ float g_Et[KCODE * DDIM];     // k-major codebook
__device__ float g_invcs[KCODE];
__device__ float g_loss;

// ---------------------------------------------------------------------------
__global__ void k0_prep(const float* __restrict__ E) {
    int stride = gridDim.x * blockDim.x;
    for (int i = blockIdx.x * blockDim.x + threadIdx.x; i < KCODE * DDIM; i += stride) {
        int k  = i >> 8;
        int dd = i & 255;
        g_Et[i]   = E[dd * KCODE + k];
        g_esum[i] = 0.0f;
        if (i < KCODE) g_counts[i] = 0.0f;
        if (i == 0)    g_loss = 0.0f;
    }
}

__global__ void k0_enorm() {
    int gw   = (blockIdx.x * blockDim.x + threadIdx.x) >> 5;
    int lane = threadIdx.x & 31;
    if (gw >= KCODE) return;
    const float4* row = (const float4*)(g_Et + (size_t)gw * DDIM);
    float s = 0.f;
    float4 a = row[lane];
    s += a.x * a.x + a.y * a.y + a.z * a.z + a.w * a.w;
    float4 b = row[lane + 32];
    s += b.x * b.x + b.y * b.y + b.z * b.z + b.w * b.w;
    #pragma unroll
    for (int o = 16; o; o >>= 1) s += __shfl_xor_sync(0xffffffffu, s, o);
    if (lane == 0) g_enorm[gw] = s;
}

// ---------------------------------------------------------------------------
// k1: FFMA2-packed GEMM + argmin + fused epilogue.
// 256 threads, BM=128, BN=128 (8 chunks), BK=16.
// A preloaded transposed to smem once; B streamed via cp.async 4-buf ring.
// ---------------------------------------------------------------------------
#define BM 128
#define BN 128
#define BK 16
#define APITCH 132
#define NBUF 4
#define NDS (DDIM / BK)   // 16
#define SMEM_K1 (DDIM * APITCH * 4 + NBUF * BK * BN * 4)  // 135168 + 32768

#define FMA2(c,a,b) asm("fma.rn.f32x2 %0, %1, %2, %3;" : "=l"(c) : "l"(a), "l"(b), "l"(c))
#define PACKDUP(d,f) asm("mov.b64 %0, {%1, %1};" : "=l"(d) : "r"(__float_as_uint(f)))

__device__ __forceinline__ void cp16(uint32_t dst, const void* src) {
    asm volatile("cp.async.cg.shared.global [%0], [%1], 16;" :: "r"(dst), "l"(src));
}

__device__ __forceinline__ void cp_tile(const float* __restrict__ E, int k0, int ds,
                                        int buf, uint32_t bs_u32, int tid) {
    int f = tid * 8;           // 8 floats / thread (32B)
    int d = f >> 7;            // 0..15
    int c = f & 127;
    const float* src = E + (size_t)(ds * BK + d) * KCODE + k0 + c;
    uint32_t dst = bs_u32 + (uint32_t)(((buf * BK + d) * BN + c) * 4);
    cp16(dst, src);
    cp16(dst + 16, src + 4);
    asm volatile("cp.async.commit_group;");
}

__global__ __launch_bounds__(256)
void k1_main(const float* __restrict__ z, const float* __restrict__ E,
             float* __restrict__ out_zq) {
    extern __shared__ float smem[];
    float* As = smem;                          // [DDIM][APITCH]
    float* Bs = smem + DDIM * APITCH;          // [NBUF][BK][BN]
    uint32_t bs_u32 = (uint32_t)__cvta_generic_to_shared(Bs);

    const int tid  = threadIdx.x;
    const int lane = tid & 31;     // = tx: cols tx*4 .. tx*4+3
    const int ty   = tid >> 5;     // warp: rows ty*16 .. ty*16+15
    const int tx4  = lane * 4;
    const int ty16 = ty * 16;
    const int row0 = blockIdx.x * BM;

    float bv[16];
    int   bi[16];
    #pragma unroll
    for (int r = 0; r < 16; ++r) { bv[r] = 3.4e38f; bi[r] = 0; }

    for (int kc = 0; kc < KCODE / BN; ++kc) {
        const int k0 = kc * BN;
        // pipeline prologue: 2 B tiles in flight
        cp_tile(E, k0, 0, 0, bs_u32, tid);
        cp_tile(E, k0, 1, 1, bs_u32, tid);

        if (kc == 0) {
            // preload full A block (transposed) once; overlaps with B cp flight
            #pragma unroll 4
            for (int it = 0; it < 32; ++it) {
                int v  = tid + it * 256;       // float4 index
                int r  = v >> 6;
                int c4 = v & 63;
                float4 zv = *(const float4*)(z + (size_t)(row0 + r) * DDIM + c4 * 4);
                float* col = As + (size_t)(c4 * 4) * APITCH + r;
                col[0 * APITCH] = zv.x;
                col[1 * APITCH] = zv.y;
                col[2 * APITCH] = zv.z;
                col[3 * APITCH] = zv.w;
            }
        }

        unsigned long long acc[8][4];
        #pragma unroll
        for (int i = 0; i < 8; ++i)
            #pragma unroll
            for (int j = 0; j < 4; ++j) acc[i][j] = 0ull;

        for (int ds = 0; ds < NDS; ++ds) {
            if (ds + 2 < NDS) {
                cp_tile(E, k0, ds + 2, (ds + 2) & 3, bs_u32, tid);
                asm volatile("cp.async.wait_group 2;");
            } else if (ds + 1 < NDS) {
                asm volatile("cp.async.wait_group 1;");
            } else {
                asm volatile("cp.async.wait_group 0;");
            }
            __syncthreads();

            const int d0 = ds * BK;
            const float* BsBuf = Bs + (size_t)(ds & 3) * BK * BN;
            #pragma unroll
            for (int kk = 0; kk < BK; ++kk) {
                const float* arow = As + (size_t)(d0 + kk) * APITCH + ty16;
                ulonglong2 a01 = *(const ulonglong2*)(arow);
                ulonglong2 a23 = *(const ulonglong2*)(arow + 4);
                ulonglong2 a45 = *(const ulonglong2*)(arow + 8);
                ulonglong2 a67 = *(const ulonglong2*)(arow + 12);
                float4 bf = *(const float4*)(BsBuf + kk * BN + tx4);
                unsigned long long b0, b1, b2, b3;
                PACKDUP(b0, bf.x); PACKDUP(b1, bf.y);
                PACKDUP(b2, bf.z); PACKDUP(b3, bf.w);
                unsigned long long ap[8] = {a01.x, a01.y, a23.x, a23.y,
                                            a45.x, a45.y, a67.x, a67.y};
                #pragma unroll
                for (int ip = 0; ip < 8; ++ip) {
                    FMA2(acc[ip][0], ap[ip], b0);
                    FMA2(acc[ip][1], ap[ip], b1);
                    FMA2(acc[ip][2], ap[ip], b2);
                    FMA2(acc[ip][3], ap[ip], b3);
                }
            }
        }

        // per-lane argmin update (dist = ||e||^2 - 2*dot; ||z||^2 added later)
        float4 en = *(const float4*)(g_enorm + k0 + tx4);
        float enj[4] = {en.x, en.y, en.z, en.w};
        #pragma unroll
        for (int ip = 0; ip < 8; ++ip) {
            #pragma unroll
            for (int j = 0; j < 4; ++j) {
                unsigned long long p = acc[ip][j];
                float lo = __uint_as_float((unsigned)p);
                float hi = __uint_as_float((unsigned)(p >> 32));
                float slo = enj[j] - 2.0f * lo;
                float shi = enj[j] - 2.0f * hi;
                int col = k0 + tx4 + j;
                if (slo < bv[2 * ip])     { bv[2 * ip]     = slo; bi[2 * ip]     = col; }
                if (shi < bv[2 * ip + 1]) { bv[2 * ip + 1] = shi; bi[2 * ip + 1] = col; }
            }
        }
    }

    // final per-row butterfly reduction + fused epilogue (warp-private rows)
    float lossacc = 0.f;
    #pragma unroll
    for (int r = 0; r < 16; ++r) {
        float v = bv[r];
        int   i = bi[r];
        #pragma unroll
        for (int o = 16; o; o >>= 1) {
            float ov = __shfl_xor_sync(0xffffffffu, v, o);
            int   oi = __shfl_xor_sync(0xffffffffu, i, o);
            if (ov < v || (ov == v && oi < i)) { v = ov; i = oi; }
        }
        int R = row0 + ty16 + r;
        const float4* zrow = (const float4*)(z + (size_t)R * DDIM);
        float4*       orow = (float4*)(out_zq + (size_t)R * DDIM);
        const float4* et   = (const float4*)(g_Et + (size_t)i * DDIM);
        float zsq = 0.f;
        #pragma unroll
        for (int itc = 0; itc < 2; ++itc) {
            int c = lane + itc * 32;
            float4 zv = zrow[c];
            zsq += zv.x * zv.x + zv.y * zv.y + zv.z * zv.z + zv.w * zv.w;
            float* es = g_esum + (size_t)i * DDIM + c * 4;
            atomicAdd(es + 0, zv.x);
            atomicAdd(es + 1, zv.y);
            atomicAdd(es + 2, zv.z);
            atomicAdd(es + 3, zv.w);
            orow[c] = et[c];
        }
        #pragma unroll
        for (int o = 16; o; o >>= 1) zsq += __shfl_xor_sync(0xffffffffu, zsq, o);
        if (lane == 0) {
            lossacc += zsq + v;
            atomicAdd(&g_counts[i], 1.0f);
        }
    }
    if (lane == 0) atomicAdd(&g_loss, lossacc);
}

// ---------------------------------------------------------------------------
__global__ void k2_stats(const float* __restrict__ cs_in, float* __restrict__ out,
                         long long cs_off, long long loss_off) {
    __shared__ float red[KCODE];
    int t = threadIdx.x;
    float csn = cs_in[t] * DECAY + OMD * g_counts[t];
    out[cs_off + t] = csn;
    red[t] = csn;
    __syncthreads();
    for (int s = 512; s; s >>= 1) {
        if (t < s) red[t] += red[t + s];
        __syncthreads();
    }
    float n  = red[0];
    float cs = (csn + EPSV) / (n + (float)KCODE * EPSV) * n;
    g_invcs[t] = 1.0f / cs;
    if (t == 0) out[loss_off] = VQ_COMMIT * g_loss / (float)((long long)N_TOK * DDIM);
}

__global__ void k3_emb(const float* __restrict__ emean, float* __restrict__ out,
                       long long en_off, long long emn_off) {
    int i = blockIdx.x * blockDim.x + threadIdx.x;
    if (i >= KCODE * DDIM) return;
    int dd = i >> 10;
    int k  = i & 1023;
    float emn = emean[i] * DECAY + OMD * g_esum[(size_t)k * DDIM + dd];
    out[emn_off + i] = emn;
    out[en_off + i]  = emn * g_invcs[k];
}

// ---------------------------------------------------------------------------
extern "C" void kernel_launch(void* const* d_in, const int* in_sizes, int n_in,
                              void* d_out, int out_size) {
    const float* z  = (const float*)d_in[0];
    const float* E  = (const float*)d_in[1];
    const float* cs = (const float*)d_in[2];
    const float* em = (const float*)d_in[3];
    float* out = (float*)d_out;

    long long ND = in_sizes[0];
    long long DK = in_sizes[1];
    long long K  = in_sizes[2];
    long long loss_off = ND;
    long long en_off   = ND + 1;
    long long cs_off   = en_off + DK;
    long long emn_off  = cs_off + K;

    cudaFuncSetAttribute(k1_main, cudaFuncAttributeMaxDynamicSharedMemorySize, SMEM_K1);

    k0_prep<<<512, 256>>>(E);
    k0_enorm<<<128, 256>>>();
    k1_main<<<N_TOK / BM, 256, SMEM_K1>>>(z, E, out);
    k2_stats<<<1, 1024>>>(cs, out, cs_off, loss_off);
    k3_emb<<<(KCODE * DDIM + 255) / 256, 256>>>(em, out, en_off, emn_off);
}

// round 8
// speedup vs baseline: 1.7679x; 1.0315x over previous
#include <cuda_runtime.h>
#include <cuda_bf16.h>
#include <cstdint>

#define N_TOK   65536
#define DDIM    256
#define KCODE   1024
#define DECAY   0.99f
#define OMD     0.01f
#define EPSV    1e-5f
#define VQ_COMMIT 0.25f
#define TH_RES  0.08f

#define BM 128
#define APITCH 264          // bf16 elems per A smem row (pad for ldmatrix)
#define BPITCH 72           // bf16 elems per B smem row
#define NCH 8               // 8 chunks of 128 codes
#define NTILE 32            // 8 chunks * 4 k-tiles of 64

// smem byte offsets
#define SM_AH    0
#define SM_AL    (128 * APITCH * 2)                  // 67584
#define SM_B     (2 * 128 * APITCH * 2)              // 135168
#define SPLIT_SZ (128 * BPITCH * 2)                  // 18432
#define BBUF_SZ  (2 * SPLIT_SZ)                      // 36864 (hi+lo)
#define SM_ENORM (SM_B + 2 * BBUF_SZ)                // 208896
#define SM_RED   (SM_ENORM + 4096)                   // 212992: [2][128][3] v + i
#define SM_BV    (SM_RED + 6144)                     // 219136
#define SM_BI    (SM_BV + 512)                       // 219648
#define SM_FLAGN (SM_BI + 512)                       // 220160
#define SM_FLAGS (SM_FLAGN + 16)                     // 220176
#define SMEM_K1  (SM_FLAGS + 512 + 32)               // 220720

// ---- device scratch ----
__device__ float g_Et[KCODE * DDIM];                 // [code][d] exact fp32
__device__ float g_esum[KCODE * DDIM];
__device__ float g_counts[KCODE];
__device__ float g_enorm[KCODE];
__device__ float g_invcs[KCODE];
__device__ float g_loss;
__device__ __align__(16) __nv_bfloat16 g_Bh[KCODE * DDIM];  // [code][d] hi
__device__ __align__(16) __nv_bfloat16 g_Bl[KCODE * DDIM];  // [code][d] lo

// ---- PTX helpers ----
__device__ __forceinline__ uint32_t smem_u32(const void* p) {
    uint32_t a;
    asm("{ .reg .u64 t; cvta.to.shared.u64 t, %1; cvt.u32.u64 %0, t; }" : "=r"(a) : "l"(p));
    return a;
}
__device__ __forceinline__ void cp16(uint32_t dst, const void* src) {
    asm volatile("cp.async.cg.shared.global [%0], [%1], 16;" :: "r"(dst), "l"(src));
}
__device__ __forceinline__ void cp_commit() { asm volatile("cp.async.commit_group;"); }
__device__ __forceinline__ void cp_wait0()  { asm volatile("cp.async.wait_group 0;" ::: "memory"); }
__device__ __forceinline__ void cp_wait1()  { asm volatile("cp.async.wait_group 1;" ::: "memory"); }

__device__ __forceinline__ void ldsm_x4(uint32_t* r, uint32_t a) {
    asm volatile("ldmatrix.sync.aligned.m8n8.x4.shared.b16 {%0,%1,%2,%3}, [%4];"
        : "=r"(r[0]), "=r"(r[1]), "=r"(r[2]), "=r"(r[3]) : "r"(a));
}
__device__ __forceinline__ void ldsm_x2(uint32_t* r, uint32_t a) {
    asm volatile("ldmatrix.sync.aligned.m8n8.x2.shared.b16 {%0,%1}, [%2];"
        : "=r"(r[0]), "=r"(r[1]) : "r"(a));
}
__device__ __forceinline__ void mma16816(float* d, const uint32_t* a, const uint32_t* b) {
    asm volatile("mma.sync.aligned.m16n8k16.row.col.f32.bf16.bf16.f32 "
        "{%0,%1,%2,%3}, {%4,%5,%6,%7}, {%8,%9}, {%0,%1,%2,%3};"
        : "+f"(d[0]), "+f"(d[1]), "+f"(d[2]), "+f"(d[3])
        : "r"(a[0]), "r"(a[1]), "r"(a[2]), "r"(a[3]), "r"(b[0]), "r"(b[1]));
}
__device__ __forceinline__ uint32_t pack_bf2(float x, float y) {
    __nv_bfloat16 a = __float2bfloat16(x), b = __float2bfloat16(y);
    return ((uint32_t)__bfloat16_as_ushort(b) << 16) | (uint32_t)__bfloat16_as_ushort(a);
}

// Reference-matching fp32 distance: STRICTLY sequential FFMA chain over
// ascending d (bitwise identical to the round-2 kernel that matched the
// reference argmin on every token), then dist = fmaf(-2, dot, enorm).
__device__ __forceinline__ float chain_dist_f32(const float* __restrict__ zr,
                                                const float* __restrict__ er,
                                                float en) {
    float dot = 0.0f;
    #pragma unroll 16
    for (int i = 0; i < DDIM; ++i) {
        dot = fmaf(zr[i], er[i], dot);
    }
    return fmaf(-2.0f, dot, en);
}

// ---------------------------------------------------------------------------
// k0: exact Et [code][d], bf16 split images, zero stats
// ---------------------------------------------------------------------------
__global__ void k0_prep(const float* __restrict__ E) {
    int stride = gridDim.x * blockDim.x;
    for (int i = blockIdx.x * blockDim.x + threadIdx.x; i < KCODE * DDIM; i += stride) {
        int k = i >> 8, dd = i & 255;
        float x = E[dd * KCODE + k];
        g_Et[i] = x;
        g_esum[i] = 0.0f;
        if (i < KCODE) g_counts[i] = 0.0f;
        if (i == 0)    g_loss = 0.0f;
        __nv_bfloat16 h = __float2bfloat16(x);
        __nv_bfloat16 l = __float2bfloat16(x - __bfloat162float(h));
        g_Bh[i] = h;
        g_Bl[i] = l;
    }
}

__global__ void k0_enorm() {
    int gw = (blockIdx.x * blockDim.x + threadIdx.x) >> 5;
    int lane = threadIdx.x & 31;
    if (gw >= KCODE) return;
    const float4* row = (const float4*)(g_Et + (size_t)gw * DDIM);
    float s = 0.f;
    float4 a = row[lane];       s += a.x*a.x + a.y*a.y + a.z*a.z + a.w*a.w;
    float4 b = row[lane + 32];  s += b.x*b.x + b.y*b.y + b.z*b.z + b.w*b.w;
    #pragma unroll
    for (int o = 16; o; o >>= 1) s += __shfl_xor_sync(0xffffffffu, s, o);
    if (lane == 0) g_enorm[gw] = s;
}

// ---------------------------------------------------------------------------
#define UPD3(v, ix, d, n) do { \
    if ((d) < (v)[0] || ((d) == (v)[0] && (n) < (ix)[0])) { \
        (v)[2]=(v)[1]; (ix)[2]=(ix)[1]; (v)[1]=(v)[0]; (ix)[1]=(ix)[0]; (v)[0]=(d); (ix)[0]=(n); \
    } else if ((d) < (v)[1] || ((d) == (v)[1] && (n) < (ix)[1])) { \
        (v)[2]=(v)[1]; (ix)[2]=(ix)[1]; (v)[1]=(d); (ix)[1]=(n); \
    } else if ((d) < (v)[2] || ((d) == (v)[2] && (n) < (ix)[2])) { \
        (v)[2]=(d); (ix)[2]=(n); \
    } } while (0)

// ---------------------------------------------------------------------------
// k1: HMMA split-GEMM + top-3 argmin + reference-fp32 rescore + fused epilogue
// ---------------------------------------------------------------------------
__global__ __launch_bounds__(256)
void k1_main(const float* __restrict__ z, float* __restrict__ out_zq) {
    extern __shared__ unsigned char sm[];
    const uint32_t sb = smem_u32(sm);
    float* en_s = (float*)(sm + SM_ENORM);
    float* redv = (float*)(sm + SM_RED);            // [2][128][3]
    int*   redi = (int*)(sm + SM_RED + 3072);       // [2][128][3]
    float* bv_s = (float*)(sm + SM_BV);
    int*   bi_s = (int*)(sm + SM_BI);
    int*   flagn = (int*)(sm + SM_FLAGN);
    int*   flags = (int*)(sm + SM_FLAGS);

    const int tid = threadIdx.x, lane = tid & 31, wid = tid >> 5;
    const int wm = wid >> 1, wn = wid & 1;
    const int row0 = blockIdx.x * BM;

    // ---- stage(0) of B ----
    {
        int split = tid >> 7, n = tid & 127;
        const __nv_bfloat16* src = (split ? g_Bl : g_Bh) + (size_t)n * DDIM;
        uint32_t dst = sb + SM_B + split * SPLIT_SZ + n * BPITCH * 2;
        #pragma unroll
        for (int j = 0; j < 8; ++j) cp16(dst + j * 16, src + j * 8);
        cp_commit();
    }
    if (tid == 0) *flagn = 0;

    // ---- A block load + bf16 split into smem ----
    #pragma unroll 4
    for (int it = 0; it < 32; ++it) {
        int v = tid + it * 256;
        int r = v >> 6, c4 = v & 63;
        float4 x = *(const float4*)(z + (size_t)(row0 + r) * DDIM + c4 * 4);
        float h0f = __bfloat162float(__float2bfloat16(x.x));
        float h1f = __bfloat162float(__float2bfloat16(x.y));
        float h2f = __bfloat162float(__float2bfloat16(x.z));
        float h3f = __bfloat162float(__float2bfloat16(x.w));
        uint2 hh, ll;
        hh.x = pack_bf2(x.x, x.y); hh.y = pack_bf2(x.z, x.w);
        ll.x = pack_bf2(x.x - h0f, x.y - h1f); ll.y = pack_bf2(x.z - h2f, x.w - h3f);
        *(uint2*)(sm + SM_AH + (size_t)(r * APITCH + c4 * 4) * 2) = hh;
        *(uint2*)(sm + SM_AL + (size_t)(r * APITCH + c4 * 4) * 2) = ll;
    }
    *(float4*)(en_s + tid * 4) = *(const float4*)(g_enorm + tid * 4);

    const uint32_t aAddrH = sb + SM_AH + (uint32_t)(((wm * 32 + (lane & 15)) * APITCH + (lane >> 4) * 8) * 2);
    const uint32_t aAddrL = aAddrH + (SM_AL - SM_AH);
    const int l15 = lane & 15;
    const uint32_t boff = (uint32_t)(((wn * 64 + (l15 & 7)) * BPITCH + ((l15 >> 3) & 1) * 8) * 2);

    float acc[2][8][4];
    float tv[4][3];
    int   ti[4][3];
    #pragma unroll
    for (int s = 0; s < 4; ++s) { tv[s][0] = tv[s][1] = tv[s][2] = 3.4e38f; ti[s][0] = ti[s][1] = ti[s][2] = 0; }

    for (int kt = 0; kt < NTILE; ++kt) {
        const int c = kt >> 2, kq = kt & 3, buf = kt & 1;
        if (kt + 1 < NTILE) {
            int nc = (kt + 1) >> 2, nq = (kt + 1) & 3, nb = (kt + 1) & 1;
            int split = tid >> 7, n = tid & 127;
            const __nv_bfloat16* src = (split ? g_Bl : g_Bh) + (size_t)(nc * 128 + n) * DDIM + nq * 64;
            uint32_t dst = sb + SM_B + nb * BBUF_SZ + split * SPLIT_SZ + n * BPITCH * 2;
            #pragma unroll
            for (int j = 0; j < 8; ++j) cp16(dst + j * 16, src + j * 8);
            cp_commit();
            cp_wait1();
        } else {
            cp_wait0();
        }
        __syncthreads();

        if (kq == 0) {
            #pragma unroll
            for (int i = 0; i < 2; ++i)
                #pragma unroll
                for (int j = 0; j < 8; ++j)
                    #pragma unroll
                    for (int r = 0; r < 4; ++r) acc[i][j][r] = 0.f;
        }

        const uint32_t bBase = sb + SM_B + buf * BBUF_SZ + boff;
        #pragma unroll
        for (int s = 0; s < 4; ++s) {
            const uint32_t ka = (uint32_t)((kq * 64 + s * 16) * 2);
            uint32_t ah0[4], ah1[4], al0[4], al1[4];
            ldsm_x4(ah0, aAddrH + ka);
            ldsm_x4(ah1, aAddrH + ka + 16 * APITCH * 2);
            ldsm_x4(al0, aAddrL + ka);
            ldsm_x4(al1, aAddrL + ka + 16 * APITCH * 2);
            const uint32_t bk = bBase + s * 32;
            #pragma unroll
            for (int j = 0; j < 8; ++j) {
                uint32_t bh[2], bl[2];
                ldsm_x2(bh, bk + j * (8 * BPITCH * 2));
                ldsm_x2(bl, bk + SPLIT_SZ + j * (8 * BPITCH * 2));
                mma16816(acc[0][j], ah0, bh);
                mma16816(acc[1][j], ah1, bh);
                mma16816(acc[0][j], ah0, bl);
                mma16816(acc[1][j], ah1, bl);
                mma16816(acc[0][j], al0, bh);
                mma16816(acc[1][j], al1, bh);
            }
        }

        if (kq == 3) {
            const int nb0 = c * 128 + wn * 64 + 2 * (lane & 3);
            #pragma unroll
            for (int j = 0; j < 8; ++j) {
                int n0 = nb0 + j * 8;
                float e0 = en_s[n0], e1 = en_s[n0 + 1];
                #pragma unroll
                for (int i = 0; i < 2; ++i) {
                    float d0 = e0 - 2.0f * acc[i][j][0];
                    float d1 = e1 - 2.0f * acc[i][j][1];
                    float d2 = e0 - 2.0f * acc[i][j][2];
                    float d3 = e1 - 2.0f * acc[i][j][3];
                    UPD3(tv[i*2],   ti[i*2],   d0, n0);
                    UPD3(tv[i*2],   ti[i*2],   d1, n0 + 1);
                    UPD3(tv[i*2+1], ti[i*2+1], d2, n0);
                    UPD3(tv[i*2+1], ti[i*2+1], d3, n0 + 1);
                }
            }
        }
        __syncthreads();
    }

    // ---- quad merge ----
    #pragma unroll
    for (int slot = 0; slot < 4; ++slot) {
        #pragma unroll
        for (int mask = 1; mask <= 2; mask <<= 1) {
            float ov0 = __shfl_xor_sync(0xffffffffu, tv[slot][0], mask);
            float ov1 = __shfl_xor_sync(0xffffffffu, tv[slot][1], mask);
            float ov2 = __shfl_xor_sync(0xffffffffu, tv[slot][2], mask);
            int   oi0 = __shfl_xor_sync(0xffffffffu, ti[slot][0], mask);
            int   oi1 = __shfl_xor_sync(0xffffffffu, ti[slot][1], mask);
            int   oi2 = __shfl_xor_sync(0xffffffffu, ti[slot][2], mask);
            UPD3(tv[slot], ti[slot], ov0, oi0);
            UPD3(tv[slot], ti[slot], ov1, oi1);
            UPD3(tv[slot], ti[slot], ov2, oi2);
        }
    }
    if ((lane & 3) == 0) {
        #pragma unroll
        for (int slot = 0; slot < 4; ++slot) {
            int row = wm * 32 + (slot >> 1) * 16 + (slot & 1) * 8 + (lane >> 2);
            int base = (wn * 128 + row) * 3;
            redv[base + 0] = tv[slot][0]; redv[base + 1] = tv[slot][1]; redv[base + 2] = tv[slot][2];
            redi[base + 0] = ti[slot][0]; redi[base + 1] = ti[slot][1]; redi[base + 2] = ti[slot][2];
        }
    }
    __syncthreads();

    // ---- per-row finalize (threads 0..127): reference-fp32 rescore ----
    if (tid < 128) {
        float v[3]; int ix[3];
        int b0 = tid * 3, b1 = (128 + tid) * 3;
        v[0] = redv[b0]; v[1] = redv[b0 + 1]; v[2] = redv[b0 + 2];
        ix[0] = redi[b0]; ix[1] = redi[b0 + 1]; ix[2] = redi[b0 + 2];
        UPD3(v, ix, redv[b1],     redi[b1]);
        UPD3(v, ix, redv[b1 + 1], redi[b1 + 1]);
        UPD3(v, ix, redv[b1 + 2], redi[b1 + 2]);

        float bd = v[0]; int bk = ix[0];
        if (v[2] - v[0] < TH_RES) {
            int s = atomicAdd(flagn, 1);
            flags[s] = tid;                      // full chain-fp32 rescan later
        } else if (v[1] - v[0] < TH_RES) {
            // chain-fp32 rescore of {ix0, ix1}; tie -> lower index
            const float* zr = z + (size_t)(row0 + tid) * DDIM;
            int ka = min(ix[0], ix[1]), kb = max(ix[0], ix[1]);
            float da = chain_dist_f32(zr, g_Et + (size_t)ka * DDIM, en_s[ka]);
            float db = chain_dist_f32(zr, g_Et + (size_t)kb * DDIM, en_s[kb]);
            if (db < da) { bd = db; bk = kb; }
            else         { bd = da; bk = ka; }
        }
        bv_s[tid] = bd;
        bi_s[tid] = bk;
    }
    __syncthreads();

    // ---- rare full chain-fp32 rescan (warp-cooperative) ----
    int nf = *flagn;
    for (int f = wid; f < nf; f += 8) {
        int row = flags[f];
        const float* zr = z + (size_t)(row0 + row) * DDIM;
        float bd = 3.4e38f; int bk = 0x7fffffff;
        for (int k = lane; k < KCODE; k += 32) {
            float d = chain_dist_f32(zr, g_Et + (size_t)k * DDIM, en_s[k]);
            if (d < bd) { bd = d; bk = k; }
        }
        #pragma unroll
        for (int o = 16; o; o >>= 1) {
            float ov = __shfl_xor_sync(0xffffffffu, bd, o);
            int   ok = __shfl_xor_sync(0xffffffffu, bk, o);
            if (ov < bd || (ov == bd && ok < bk)) { bd = ov; bk = ok; }
        }
        if (lane == 0) { bv_s[row] = bd; bi_s[row] = bk; }
    }
    __syncthreads();

    // ---- fused epilogue ----
    float lossacc = 0.f;
    #pragma unroll
    for (int rr = 0; rr < 16; ++rr) {
        int r = wid * 16 + rr;
        int R = row0 + r;
        int k = bi_s[r];
        const float4* zrow = (const float4*)(z + (size_t)R * DDIM);
        float4*       orow = (float4*)(out_zq + (size_t)R * DDIM);
        const float4* et   = (const float4*)(g_Et + (size_t)k * DDIM);
        float zsq = 0.f;
        #pragma unroll
        for (int itc = 0; itc < 2; ++itc) {
            int cidx = lane + itc * 32;
            float4 zv = zrow[cidx];
            zsq += zv.x * zv.x + zv.y * zv.y + zv.z * zv.z + zv.w * zv.w;
            float* es = g_esum + (size_t)k * DDIM + cidx * 4;
            atomicAdd(es + 0, zv.x);
            atomicAdd(es + 1, zv.y);
            atomicAdd(es + 2, zv.z);
            atomicAdd(es + 3, zv.w);
            orow[cidx] = et[cidx];
        }
        #pragma unroll
        for (int o = 16; o; o >>= 1) zsq += __shfl_xor_sync(0xffffffffu, zsq, o);
        if (lane == 0) {
            lossacc += zsq + bv_s[r];
            atomicAdd(&g_counts[k], 1.0f);
        }
    }
    if (lane == 0) atomicAdd(&g_loss, lossacc);
}

// ---------------------------------------------------------------------------
__global__ void k2_stats(const float* __restrict__ cs_in, float* __restrict__ out,
                         long long cs_off, long long loss_off) {
    __shared__ float red[KCODE];
    int t = threadIdx.x;
    float csn = cs_in[t] * DECAY + OMD * g_counts[t];
    out[cs_off + t] = csn;
    red[t] = csn;
    __syncthreads();
    for (int s = 512; s; s >>= 1) {
        if (t < s) red[t] += red[t + s];
        __syncthreads();
    }
    float n  = red[0];
    float cs = (csn + EPSV) / (n + (float)KCODE * EPSV) * n;
    g_invcs[t] = 1.0f / cs;
    if (t == 0) out[loss_off] = VQ_COMMIT * g_loss / (float)((long long)N_TOK * DDIM);
}

__global__ void k3_emb(const float* __restrict__ emean, float* __restrict__ out,
                       long long en_off, long long emn_off) {
    int i = blockIdx.x * blockDim.x + threadIdx.x;
    if (i >= KCODE * DDIM) return;
    int dd = i >> 10;
    int k  = i & 1023;
    float emn = emean[i] * DECAY + OMD * g_esum[(size_t)k * DDIM + dd];
    out[emn_off + i] = emn;
    out[en_off + i]  = emn * g_invcs[k];
}

// ---------------------------------------------------------------------------
extern "C" void kernel_launch(void* const* d_in, const int* in_sizes, int n_in,
                              void* d_out, int out_size) {
    const float* z  = (const float*)d_in[0];
    const float* E  = (const float*)d_in[1];
    const float* cs = (const float*)d_in[2];
    const float* em = (const float*)d_in[3];
    float* out = (float*)d_out;

    long long ND = in_sizes[0];
    long long DK = in_sizes[1];
    long long K  = in_sizes[2];
    long long loss_off = ND;
    long long en_off   = ND + 1;
    long long cs_off   = en_off + DK;
    long long emn_off  = cs_off + K;

    cudaFuncSetAttribute(k1_main, cudaFuncAttributeMaxDynamicSharedMemorySize, SMEM_K1);

    k0_prep<<<512, 256>>>(E);
    k0_enorm<<<128, 256>>>();
    k1_main<<<N_TOK / BM, 256, SMEM_K1>>>(z, out);
    k2_stats<<<1, 1024>>>(cs, out, cs_off, loss_off);
    k3_emb<<<(KCODE * DDIM + 255) / 256, 256>>>(em, out, en_off, emn_off);
}

// round 9
// speedup vs baseline: 2.0360x; 1.1517x over previous
#include <cuda_runtime.h>
#include <cuda_bf16.h>
#include <cstdint>

#define N_TOK   65536
#define DDIM    256
#define KCODE   1024
#define DECAY   0.99f
#define OMD     0.01f
#define EPSV    1e-5f
#define VQ_COMMIT 0.25f
#define TH_RES  0.8f

#define BM 128
#define APITCH 264          // bf16 elems per A smem row (pad for ldmatrix)
#define BPITCH 72           // bf16 elems per B smem row
#define NTILE 32            // 8 chunks * 4 k-tiles of 64

// smem byte offsets
#define SM_AH    0
#define A_SZ     (128 * APITCH * 2)                  // 67584
#define SM_B     A_SZ
#define BBUF     (128 * BPITCH * 2)                  // 18432 (hi only)
#define SM_ENORM (SM_B + 2 * BBUF)                   // 104448
#define SM_CANDV (SM_ENORM + 4096)                   // 108544: [128][8][3] float
#define SM_CANDI (SM_CANDV + 12288)                  // 120832: [128][8][3] int
#define SM_BV    (SM_CANDI + 12288)                  // 133120
#define SM_BI    (SM_BV + 512)                       // 133632
#define SM_FLAGN (SM_BI + 512)                       // 134144
#define SM_FLAGS (SM_FLAGN + 16)                     // 134160
#define SMEM_K1  (SM_FLAGS + 544)                    // 134704

// ---- device scratch ----
__device__ float g_Et[KCODE * DDIM];                 // [code][d] exact fp32
__device__ float g_esum[KCODE * DDIM];
__device__ float g_counts[KCODE];
__device__ float g_enorm[KCODE];
__device__ float g_invcs[KCODE];
__device__ float g_loss;
__device__ __align__(16) __nv_bfloat16 g_Bh[KCODE * DDIM];  // [code][d] hi

// ---- PTX helpers ----
__device__ __forceinline__ uint32_t smem_u32(const void* p) {
    uint32_t a;
    asm("{ .reg .u64 t; cvta.to.shared.u64 t, %1; cvt.u32.u64 %0, t; }" : "=r"(a) : "l"(p));
    return a;
}
__device__ __forceinline__ void cp16(uint32_t dst, const void* src) {
    asm volatile("cp.async.cg.shared.global [%0], [%1], 16;" :: "r"(dst), "l"(src));
}
__device__ __forceinline__ void cp_commit() { asm volatile("cp.async.commit_group;"); }
__device__ __forceinline__ void cp_wait0()  { asm volatile("cp.async.wait_group 0;" ::: "memory"); }
__device__ __forceinline__ void cp_wait1()  { asm volatile("cp.async.wait_group 1;" ::: "memory"); }

__device__ __forceinline__ void ldsm_x4(uint32_t* r, uint32_t a) {
    asm volatile("ldmatrix.sync.aligned.m8n8.x4.shared.b16 {%0,%1,%2,%3}, [%4];"
        : "=r"(r[0]), "=r"(r[1]), "=r"(r[2]), "=r"(r[3]) : "r"(a));
}
__device__ __forceinline__ void ldsm_x2(uint32_t* r, uint32_t a) {
    asm volatile("ldmatrix.sync.aligned.m8n8.x2.shared.b16 {%0,%1}, [%2];"
        : "=r"(r[0]), "=r"(r[1]) : "r"(a));
}
__device__ __forceinline__ void mma16816(float* d, const uint32_t* a, const uint32_t* b) {
    asm volatile("mma.sync.aligned.m16n8k16.row.col.f32.bf16.bf16.f32 "
        "{%0,%1,%2,%3}, {%4,%5,%6,%7}, {%8,%9}, {%0,%1,%2,%3};"
        : "+f"(d[0]), "+f"(d[1]), "+f"(d[2]), "+f"(d[3])
        : "r"(a[0]), "r"(a[1]), "r"(a[2]), "r"(a[3]), "r"(b[0]), "r"(b[1]));
}
__device__ __forceinline__ uint32_t pack_bf2(float x, float y) {
    __nv_bfloat16 a = __float2bfloat16(x), b = __float2bfloat16(y);
    return ((uint32_t)__bfloat16_as_ushort(b) << 16) | (uint32_t)__bfloat16_as_ushort(a);
}

// Reference-matching fp32 distance: strictly sequential FFMA chain over
// ascending d (empirically bit-matches the reference argmin), then
// dist = fmaf(-2, dot, enorm).
__device__ __forceinline__ float chain_dist_f32(const float* __restrict__ zr,
                                                const float* __restrict__ er,
                                                float en) {
    float dot = 0.0f;
    #pragma unroll 16
    for (int i = 0; i < DDIM; ++i) {
        dot = fmaf(zr[i], er[i], dot);
    }
    return fmaf(-2.0f, dot, en);
}

// ---------------------------------------------------------------------------
// k0: exact Et [code][d], bf16 hi image, zero stats
// ---------------------------------------------------------------------------
__global__ void k0_prep(const float* __restrict__ E) {
    int stride = gridDim.x * blockDim.x;
    for (int i = blockIdx.x * blockDim.x + threadIdx.x; i < KCODE * DDIM; i += stride) {
        int k = i >> 8, dd = i & 255;
        float x = E[dd * KCODE + k];
        g_Et[i] = x;
        g_esum[i] = 0.0f;
        if (i < KCODE) g_counts[i] = 0.0f;
        if (i == 0)    g_loss = 0.0f;
        g_Bh[i] = __float2bfloat16(x);
    }
}

__global__ void k0_enorm() {
    int gw = (blockIdx.x * blockDim.x + threadIdx.x) >> 5;
    int lane = threadIdx.x & 31;
    if (gw >= KCODE) return;
    const float4* row = (const float4*)(g_Et + (size_t)gw * DDIM);
    float s = 0.f;
    float4 a = row[lane];       s += a.x*a.x + a.y*a.y + a.z*a.z + a.w*a.w;
    float4 b = row[lane + 32];  s += b.x*b.x + b.y*b.y + b.z*b.z + b.w*b.w;
    #pragma unroll
    for (int o = 16; o; o >>= 1) s += __shfl_xor_sync(0xffffffffu, s, o);
    if (lane == 0) g_enorm[gw] = s;
}

// ---------------------------------------------------------------------------
#define UPD3(v, ix, d, n) do { \
    if ((d) < (v)[0] || ((d) == (v)[0] && (n) < (ix)[0])) { \
        (v)[2]=(v)[1]; (ix)[2]=(ix)[1]; (v)[1]=(v)[0]; (ix)[1]=(ix)[0]; (v)[0]=(d); (ix)[0]=(n); \
    } else if ((d) < (v)[1] || ((d) == (v)[1] && (n) < (ix)[1])) { \
        (v)[2]=(v)[1]; (ix)[2]=(ix)[1]; (v)[1]=(d); (ix)[1]=(n); \
    } else if ((d) < (v)[2] || ((d) == (v)[2] && (n) < (ix)[2])) { \
        (v)[2]=(d); (ix)[2]=(n); \
    } } while (0)

// ---------------------------------------------------------------------------
// k1: hh-only HMMA GEMM + per-lane top-3 candidates + chain-fp32 rescore
// ---------------------------------------------------------------------------
__global__ __launch_bounds__(256)
void k1_main(const float* __restrict__ z, float* __restrict__ out_zq) {
    extern __shared__ unsigned char sm[];
    const uint32_t sb = smem_u32(sm);
    float* en_s  = (float*)(sm + SM_ENORM);
    float* candv = (float*)(sm + SM_CANDV);
    int*   candi = (int*)(sm + SM_CANDI);
    float* bv_s  = (float*)(sm + SM_BV);
    int*   bi_s  = (int*)(sm + SM_BI);
    int*   flagn = (int*)(sm + SM_FLAGN);
    int*   flags = (int*)(sm + SM_FLAGS);

    const int tid = threadIdx.x, lane = tid & 31, wid = tid >> 5;
    const int wm = wid >> 1, wn = wid & 1;
    const int row0 = blockIdx.x * BM;

    // ---- stage tile 0 of B (hi only): 128 codes x 64 dims ----
    {
        int n = tid >> 1, half = tid & 1;
        const __nv_bfloat16* src = g_Bh + (size_t)n * DDIM + half * 32;
        uint32_t dst = sb + SM_B + n * (BPITCH * 2) + half * 64;
        #pragma unroll
        for (int j = 0; j < 4; ++j) cp16(dst + j * 16, src + j * 8);
        cp_commit();
    }
    if (tid == 0) *flagn = 0;

    // ---- A block load + bf16-hi into smem ----
    #pragma unroll 4
    for (int it = 0; it < 32; ++it) {
        int v = tid + it * 256;
        int r = v >> 6, c4 = v & 63;
        float4 x = *(const float4*)(z + (size_t)(row0 + r) * DDIM + c4 * 4);
        uint2 hh;
        hh.x = pack_bf2(x.x, x.y); hh.y = pack_bf2(x.z, x.w);
        *(uint2*)(sm + SM_AH + (size_t)(r * APITCH + c4 * 4) * 2) = hh;
    }
    *(float4*)(en_s + tid * 4) = *(const float4*)(g_enorm + tid * 4);

    const uint32_t aAddrH = sb + SM_AH + (uint32_t)(((wm * 32 + (lane & 15)) * APITCH + (lane >> 4) * 8) * 2);
    const int l15 = lane & 15;
    const uint32_t boff = (uint32_t)(((wn * 64 + (l15 & 7)) * BPITCH + ((l15 >> 3) & 1) * 8) * 2);

    float acc[2][8][4];
    float tv[4][3];
    int   ti[4][3];
    #pragma unroll
    for (int s = 0; s < 4; ++s) { tv[s][0] = tv[s][1] = tv[s][2] = 3.4e38f; ti[s][0] = ti[s][1] = ti[s][2] = 0; }

    for (int kt = 0; kt < NTILE; ++kt) {
        const int c = kt >> 2, kq = kt & 3, buf = kt & 1;
        if (kt + 1 < NTILE) {
            int nc = (kt + 1) >> 2, nq = (kt + 1) & 3, nb = (kt + 1) & 1;
            int n = tid >> 1, half = tid & 1;
            const __nv_bfloat16* src = g_Bh + (size_t)(nc * 128 + n) * DDIM + nq * 64 + half * 32;
            uint32_t dst = sb + SM_B + nb * BBUF + n * (BPITCH * 2) + half * 64;
            #pragma unroll
            for (int j = 0; j < 4; ++j) cp16(dst + j * 16, src + j * 8);
            cp_commit();
            cp_wait1();
        } else {
            cp_wait0();
        }
        __syncthreads();

        if (kq == 0) {
            #pragma unroll
            for (int i = 0; i < 2; ++i)
                #pragma unroll
                for (int j = 0; j < 8; ++j)
                    #pragma unroll
                    for (int r = 0; r < 4; ++r) acc[i][j][r] = 0.f;
        }

        const uint32_t bBase = sb + SM_B + buf * BBUF + boff;
        #pragma unroll
        for (int s = 0; s < 4; ++s) {
            const uint32_t ka = (uint32_t)((kq * 64 + s * 16) * 2);
            uint32_t ah0[4], ah1[4];
            ldsm_x4(ah0, aAddrH + ka);
            ldsm_x4(ah1, aAddrH + ka + 16 * APITCH * 2);
            const uint32_t bk = bBase + s * 32;
            #pragma unroll
            for (int j = 0; j < 8; ++j) {
                uint32_t bh[2];
                ldsm_x2(bh, bk + j * (8 * BPITCH * 2));
                mma16816(acc[0][j], ah0, bh);
                mma16816(acc[1][j], ah1, bh);
            }
        }

        if (kq == 3) {
            const int nb0 = c * 128 + wn * 64 + 2 * (lane & 3);
            #pragma unroll
            for (int j = 0; j < 8; ++j) {
                int n0 = nb0 + j * 8;
                float e0 = en_s[n0], e1 = en_s[n0 + 1];
                #pragma unroll
                for (int i = 0; i < 2; ++i) {
                    float d0 = e0 - 2.0f * acc[i][j][0];
                    float d1 = e1 - 2.0f * acc[i][j][1];
                    float d2 = e0 - 2.0f * acc[i][j][2];
                    float d3 = e1 - 2.0f * acc[i][j][3];
                    UPD3(tv[i*2],   ti[i*2],   d0, n0);
                    UPD3(tv[i*2],   ti[i*2],   d1, n0 + 1);
                    UPD3(tv[i*2+1], ti[i*2+1], d2, n0);
                    UPD3(tv[i*2+1], ti[i*2+1], d3, n0 + 1);
                }
            }
        }
        __syncthreads();
    }

    // ---- write all 24 per-row candidates (per-lane top-3, disjoint subsets) ----
    {
        const int lane8 = wn * 4 + (lane & 3);
        #pragma unroll
        for (int slot = 0; slot < 4; ++slot) {
            int row = wm * 32 + (slot >> 1) * 16 + (slot & 1) * 8 + (lane >> 2);
            int base = (row * 8 + lane8) * 3;
            candv[base + 0] = tv[slot][0]; candv[base + 1] = tv[slot][1]; candv[base + 2] = tv[slot][2];
            candi[base + 0] = ti[slot][0]; candi[base + 1] = ti[slot][1]; candi[base + 2] = ti[slot][2];
        }
    }
    __syncthreads();

    // ---- per-row finalize (threads 0..127) ----
    if (tid < 128) {
        const int base = tid * 24;
        float v0 = candv[base]; int i0 = candi[base];
        #pragma unroll
        for (int t = 1; t < 24; ++t) {
            float v = candv[base + t]; int i = candi[base + t];
            if (v < v0 || (v == v0 && i < i0)) { v0 = v; i0 = i; }
        }
        // min over lanes of each lane's 3rd-best (safety net)
        float m3 = candv[base + 2];
        #pragma unroll
        for (int L = 1; L < 8; ++L) m3 = fminf(m3, candv[base + L * 3 + 2]);

        // gather candidates within TH of best
        int cl[8]; int cnt = 0;
        #pragma unroll
        for (int t = 0; t < 24; ++t) {
            if (candv[base + t] < v0 + TH_RES) {
                if (cnt < 8) cl[cnt] = candi[base + t];
                ++cnt;
            }
        }

        if (m3 < v0 + TH_RES || cnt > 8) {
            int s = atomicAdd(flagn, 1);
            flags[s] = tid;                      // full chain-fp32 rescan later
            bv_s[tid] = v0; bi_s[tid] = i0;      // placeholder (overwritten)
        } else if (cnt <= 1) {
            bv_s[tid] = v0; bi_s[tid] = i0;
        } else {
            const float* zr = z + (size_t)(row0 + tid) * DDIM;
            float bd = 3.4e38f; int bk = 0x7fffffff;
            for (int t = 0; t < cnt; ++t) {
                int k = cl[t];
                float d = chain_dist_f32(zr, g_Et + (size_t)k * DDIM, en_s[k]);
                if (d < bd || (d == bd && k < bk)) { bd = d; bk = k; }
            }
            bv_s[tid] = bd; bi_s[tid] = bk;
        }
    }
    __syncthreads();

    // ---- rare full chain-fp32 rescan (warp-cooperative) ----
    int nf = *flagn;
    for (int f = wid; f < nf; f += 8) {
        int row = flags[f];
        const float* zr = z + (size_t)(row0 + row) * DDIM;
        float bd = 3.4e38f; int bk = 0x7fffffff;
        for (int k = lane; k < KCODE; k += 32) {
            float d = chain_dist_f32(zr, g_Et + (size_t)k * DDIM, en_s[k]);
            if (d < bd) { bd = d; bk = k; }
        }
        #pragma unroll
        for (int o = 16; o; o >>= 1) {
            float ov = __shfl_xor_sync(0xffffffffu, bd, o);
            int   ok = __shfl_xor_sync(0xffffffffu, bk, o);
            if (ov < bd || (ov == bd && ok < bk)) { bd = ov; bk = ok; }
        }
        if (lane == 0) { bv_s[row] = bd; bi_s[row] = bk; }
    }
    __syncthreads();

    // ---- fused epilogue ----
    float lossacc = 0.f;
    #pragma unroll
    for (int rr = 0; rr < 16; ++rr) {
        int r = wid * 16 + rr;
        int R = row0 + r;
        int k = bi_s[r];
        const float4* zrow = (const float4*)(z + (size_t)R * DDIM);
        float4*       orow = (float4*)(out_zq + (size_t)R * DDIM);
        const float4* et   = (const float4*)(g_Et + (size_t)k * DDIM);
        float zsq = 0.f;
        #pragma unroll
        for (int itc = 0; itc < 2; ++itc) {
            int cidx = lane + itc * 32;
            float4 zv = zrow[cidx];
            zsq += zv.x * zv.x + zv.y * zv.y + zv.z * zv.z + zv.w * zv.w;
            float* es = g_esum + (size_t)k * DDIM + cidx * 4;
            atomicAdd(es + 0, zv.x);
            atomicAdd(es + 1, zv.y);
            atomicAdd(es + 2, zv.z);
            atomicAdd(es + 3, zv.w);
            orow[cidx] = et[cidx];
        }
        #pragma unroll
        for (int o = 16; o; o >>= 1) zsq += __shfl_xor_sync(0xffffffffu, zsq, o);
        if (lane == 0) {
            lossacc += zsq + bv_s[r];
            atomicAdd(&g_counts[k], 1.0f);
        }
    }
    if (lane == 0) atomicAdd(&g_loss, lossacc);
}

// ---------------------------------------------------------------------------
__global__ void k2_stats(const float* __restrict__ cs_in, float* __restrict__ out,
                         long long cs_off, long long loss_off) {
    __shared__ float red[KCODE];
    int t = threadIdx.x;
    float csn = cs_in[t] * DECAY + OMD * g_counts[t];
    out[cs_off + t] = csn;
    red[t] = csn;
    __syncthreads();
    for (int s = 512; s; s >>= 1) {
        if (t < s) red[t] += red[t + s];
        __syncthreads();
    }
    float n  = red[0];
    float cs = (csn + EPSV) / (n + (float)KCODE * EPSV) * n;
    g_invcs[t] = 1.0f / cs;
    if (t == 0) out[loss_off] = VQ_COMMIT * g_loss / (float)((long long)N_TOK * DDIM);
}

__global__ void k3_emb(const float* __restrict__ emean, float* __restrict__ out,
                       long long en_off, long long emn_off) {
    int i = blockIdx.x * blockDim.x + threadIdx.x;
    if (i >= KCODE * DDIM) return;
    int dd = i >> 10;
    int k  = i & 1023;
    float emn = emean[i] * DECAY + OMD * g_esum[(size_t)k * DDIM + dd];
    out[emn_off + i] = emn;
    out[en_off + i]  = emn * g_invcs[k];
}

// ---------------------------------------------------------------------------
extern "C" void kernel_launch(void* const* d_in, const int* in_sizes, int n_in,
                              void* d_out, int out_size) {
    const float* z  = (const float*)d_in[0];
    const float* E  = (const float*)d_in[1];
    const float* cs = (const float*)d_in[2];
    const float* em = (const float*)d_in[3];
    float* out = (float*)d_out;

    long long ND = in_sizes[0];
    long long DK = in_sizes[1];
    long long K  = in_sizes[2];
    long long loss_off = ND;
    long long en_off   = ND + 1;
    long long cs_off   = en_off + DK;
    long long emn_off  = cs_off + K;

    cudaFuncSetAttribute(k1_main, cudaFuncAttributeMaxDynamicSharedMemorySize, SMEM_K1);

    k0_prep<<<512, 256>>>(E);
    k0_enorm<<<128, 256>>>();
    k1_main<<<N_TOK / BM, 256, SMEM_K1>>>(z, out);
    k2_stats<<<1, 1024>>>(cs, out, cs_off, loss_off);
    k3_emb<<<(KCODE * DDIM + 255) / 256, 256>>>(em, out, en_off, emn_off);
}

// round 10
// speedup vs baseline: 2.1346x; 1.0484x over previous
#include <cuda_runtime.h>
#include <cuda_bf16.h>
#include <cstdint>

#define N_TOK   65536
#define DDIM    256
#define KCODE   1024
#define DECAY   0.99f
#define OMD     0.01f
#define EPSV    1e-5f
#define VQ_COMMIT 0.25f
#define TH_RES  0.8f

#define BM 128
#define APITCH 264          // bf16 elems per A smem row (pad for ldmatrix)

// smem byte offsets
#define SM_AH    0
#define A_SZ     (128 * APITCH * 2)                  // 67584
#define SM_ENORM A_SZ                                // 67584
#define SM_CANDV (SM_ENORM + 4096)                   // 71680: [128][8][3] float
#define SM_CANDI (SM_CANDV + 12288)                  // 83968: [128][8][3] int
#define SM_BV    (SM_CANDI + 12288)                  // 96256
#define SM_BI    (SM_BV + 512)                       // 96768
#define SM_FLAGN (SM_BI + 512)                       // 97280
#define SM_FLAGS (SM_FLAGN + 16)                     // 97296
#define SMEM_K1  (SM_FLAGS + 544)                    // 97840

// ---- device scratch ----
__device__ float g_Et[KCODE * DDIM];                 // [code][d] exact fp32
__device__ float g_esum[KCODE * DDIM];
__device__ float g_counts[KCODE];
__device__ float g_enorm[KCODE];
__device__ float g_invcs[KCODE];
__device__ float g_loss;
// B in HMMA fragment-major order: [c(8)][wn(2)][s(16)][j(8)][lane(32)] x 8B
__device__ __align__(16) unsigned char g_Bf[8 * 2 * 16 * 8 * 32 * 8];   // 512KB

// ---- PTX helpers ----
__device__ __forceinline__ uint32_t smem_u32(const void* p) {
    uint32_t a;
    asm("{ .reg .u64 t; cvta.to.shared.u64 t, %1; cvt.u32.u64 %0, t; }" : "=r"(a) : "l"(p));
    return a;
}
__device__ __forceinline__ void ldsm_x4(uint32_t* r, uint32_t a) {
    asm volatile("ldmatrix.sync.aligned.m8n8.x4.shared.b16 {%0,%1,%2,%3}, [%4];"
        : "=r"(r[0]), "=r"(r[1]), "=r"(r[2]), "=r"(r[3]) : "r"(a));
}
__device__ __forceinline__ void mma16816(float* d, const uint32_t* a, const uint32_t* b) {
    asm volatile("mma.sync.aligned.m16n8k16.row.col.f32.bf16.bf16.f32 "
        "{%0,%1,%2,%3}, {%4,%5,%6,%7}, {%8,%9}, {%0,%1,%2,%3};"
        : "+f"(d[0]), "+f"(d[1]), "+f"(d[2]), "+f"(d[3])
        : "r"(a[0]), "r"(a[1]), "r"(a[2]), "r"(a[3]), "r"(b[0]), "r"(b[1]));
}
__device__ __forceinline__ uint32_t pack_bf2(float x, float y) {
    __nv_bfloat16 a = __float2bfloat16(x), b = __float2bfloat16(y);
    return ((uint32_t)__bfloat16_as_ushort(b) << 16) | (uint32_t)__bfloat16_as_ushort(a);
}

// Reference-matching fp32 distance: strictly sequential FFMA chain over
// ascending d (empirically bit-matches the reference argmin), then
// dist = fmaf(-2, dot, enorm).
__device__ __forceinline__ float chain_dist_f32(const float* __restrict__ zr,
                                                const float* __restrict__ er,
                                                float en) {
    float dot = 0.0f;
    #pragma unroll 16
    for (int i = 0; i < DDIM; ++i) {
        dot = fmaf(zr[i], er[i], dot);
    }
    return fmaf(-2.0f, dot, en);
}

// ---------------------------------------------------------------------------
// k0: exact Et [code][d], fragment-major bf16 B image, zero stats
// ---------------------------------------------------------------------------
__global__ void k0_prep(const float* __restrict__ E) {
    int stride = gridDim.x * blockDim.x;
    for (int i = blockIdx.x * blockDim.x + threadIdx.x; i < KCODE * DDIM; i += stride) {
        int k = i >> 8, dd = i & 255;   // code, dim
        float x = E[dd * KCODE + k];
        g_Et[i] = x;
        g_esum[i] = 0.0f;
        if (i < KCODE) g_counts[i] = 0.0f;
        if (i == 0)    g_loss = 0.0f;
        // fragment-major slot for mma.m16n8k16 B operand
        int c = k >> 7, nin = k & 127;
        int wn = nin >> 6, j = (nin >> 3) & 7, nrow = nin & 7;
        int s = dd >> 4, kin = dd & 15;
        int r = kin >> 3, kp = kin & 7, q = kp >> 1, bit = kp & 1;
        int l = nrow * 4 + q;
        int off = ((((c * 2 + wn) * 16 + s) * 8 + j) * 32 + l) * 8 + r * 4 + bit * 2;
        *(__nv_bfloat16*)(g_Bf + off) = __float2bfloat16(x);
    }
}

__global__ void k0_enorm() {
    int gw = (blockIdx.x * blockDim.x + threadIdx.x) >> 5;
    int lane = threadIdx.x & 31;
    if (gw >= KCODE) return;
    const float4* row = (const float4*)(g_Et + (size_t)gw * DDIM);
    float s = 0.f;
    float4 a = row[lane];       s += a.x*a.x + a.y*a.y + a.z*a.z + a.w*a.w;
    float4 b = row[lane + 32];  s += b.x*b.x + b.y*b.y + b.z*b.z + b.w*b.w;
    #pragma unroll
    for (int o = 16; o; o >>= 1) s += __shfl_xor_sync(0xffffffffu, s, o);
    if (lane == 0) g_enorm[gw] = s;
}

// ---------------------------------------------------------------------------
#define UPD3(v, ix, d, n) do { \
    if ((d) < (v)[0] || ((d) == (v)[0] && (n) < (ix)[0])) { \
        (v)[2]=(v)[1]; (ix)[2]=(ix)[1]; (v)[1]=(v)[0]; (ix)[1]=(ix)[0]; (v)[0]=(d); (ix)[0]=(n); \
    } else if ((d) < (v)[1] || ((d) == (v)[1] && (n) < (ix)[1])) { \
        (v)[2]=(v)[1]; (ix)[2]=(ix)[1]; (v)[1]=(d); (ix)[1]=(n); \
    } else if ((d) < (v)[2] || ((d) == (v)[2] && (n) < (ix)[2])) { \
        (v)[2]=(d); (ix)[2]=(n); \
    } } while (0)

// ---------------------------------------------------------------------------
// k1: barrier-free hh HMMA GEMM (B streamed from fragment-major gmem)
//     + per-lane top-3 candidates + chain-fp32 rescore + fused epilogue
// ---------------------------------------------------------------------------
__global__ __launch_bounds__(256)
void k1_main(const float* __restrict__ z, float* __restrict__ out_zq) {
    extern __shared__ unsigned char sm[];
    const uint32_t sb = smem_u32(sm);
    float* en_s  = (float*)(sm + SM_ENORM);
    float* candv = (float*)(sm + SM_CANDV);
    int*   candi = (int*)(sm + SM_CANDI);
    float* bv_s  = (float*)(sm + SM_BV);
    int*   bi_s  = (int*)(sm + SM_BI);
    int*   flagn = (int*)(sm + SM_FLAGN);
    int*   flags = (int*)(sm + SM_FLAGS);

    const int tid = threadIdx.x, lane = tid & 31, wid = tid >> 5;
    const int wm = wid >> 1, wn = wid & 1;
    const int row0 = blockIdx.x * BM;

    if (tid == 0) *flagn = 0;

    // ---- A block load + bf16-hi into smem ----
    #pragma unroll 4
    for (int it = 0; it < 32; ++it) {
        int v = tid + it * 256;
        int r = v >> 6, c4 = v & 63;
        float4 x = *(const float4*)(z + (size_t)(row0 + r) * DDIM + c4 * 4);
        uint2 hh;
        hh.x = pack_bf2(x.x, x.y); hh.y = pack_bf2(x.z, x.w);
        *(uint2*)(sm + SM_AH + (size_t)(r * APITCH + c4 * 4) * 2) = hh;
    }
    *(float4*)(en_s + tid * 4) = *(const float4*)(g_enorm + tid * 4);
    __syncthreads();

    const uint32_t aAddrH = sb + SM_AH + (uint32_t)(((wm * 32 + (lane & 15)) * APITCH + (lane >> 4) * 8) * 2);

    float tv[4][3];
    int   ti[4][3];
    #pragma unroll
    for (int s = 0; s < 4; ++s) { tv[s][0] = tv[s][1] = tv[s][2] = 3.4e38f; ti[s][0] = ti[s][1] = ti[s][2] = 0; }

    for (int c = 0; c < 8; ++c) {
        float acc[2][8][4];
        #pragma unroll
        for (int i = 0; i < 2; ++i)
            #pragma unroll
            for (int j = 0; j < 8; ++j)
                #pragma unroll
                for (int r = 0; r < 4; ++r) acc[i][j][r] = 0.f;

        const unsigned char* bc = g_Bf + (size_t)((c * 2 + wn) * 16) * 2048 + lane * 8;
        #pragma unroll
        for (int s = 0; s < 16; ++s) {
            // B fragments: 8 independent LDG.64 (deep MLP, L1/L2-resident stream)
            uint2 bfr[8];
            const uint2* bp = (const uint2*)(bc + s * 2048);
            #pragma unroll
            for (int j = 0; j < 8; ++j) bfr[j] = bp[j * 32];
            // A fragments from smem
            uint32_t ah0[4], ah1[4];
            const uint32_t ka = (uint32_t)(s * 32);
            ldsm_x4(ah0, aAddrH + ka);
            ldsm_x4(ah1, aAddrH + ka + 16 * APITCH * 2);
            #pragma unroll
            for (int j = 0; j < 8; ++j) {
                mma16816(acc[0][j], ah0, (const uint32_t*)&bfr[j]);
                mma16816(acc[1][j], ah1, (const uint32_t*)&bfr[j]);
            }
        }

        // fold chunk c into per-lane top-3
        const int nb0 = c * 128 + wn * 64 + 2 * (lane & 3);
        #pragma unroll
        for (int j = 0; j < 8; ++j) {
            int n0 = nb0 + j * 8;
            float e0 = en_s[n0], e1 = en_s[n0 + 1];
            #pragma unroll
            for (int i = 0; i < 2; ++i) {
                float d0 = e0 - 2.0f * acc[i][j][0];
                float d1 = e1 - 2.0f * acc[i][j][1];
                float d2 = e0 - 2.0f * acc[i][j][2];
                float d3 = e1 - 2.0f * acc[i][j][3];
                UPD3(tv[i*2],   ti[i*2],   d0, n0);
                UPD3(tv[i*2],   ti[i*2],   d1, n0 + 1);
                UPD3(tv[i*2+1], ti[i*2+1], d2, n0);
                UPD3(tv[i*2+1], ti[i*2+1], d3, n0 + 1);
            }
        }
    }

    // ---- write all 24 per-row candidates (per-lane top-3, disjoint subsets) ----
    {
        const int lane8 = wn * 4 + (lane & 3);
        #pragma unroll
        for (int slot = 0; slot < 4; ++slot) {
            int row = wm * 32 + (slot >> 1) * 16 + (slot & 1) * 8 + (lane >> 2);
            int base = (row * 8 + lane8) * 3;
            candv[base + 0] = tv[slot][0]; candv[base + 1] = tv[slot][1]; candv[base + 2] = tv[slot][2];
            candi[base + 0] = ti[slot][0]; candi[base + 1] = ti[slot][1]; candi[base + 2] = ti[slot][2];
        }
    }
    __syncthreads();

    // ---- per-row finalize (threads 0..127) ----
    if (tid < 128) {
        const int base = tid * 24;
        float v0 = candv[base]; int i0 = candi[base];
        #pragma unroll
        for (int t = 1; t < 24; ++t) {
            float v = candv[base + t]; int i = candi[base + t];
            if (v < v0 || (v == v0 && i < i0)) { v0 = v; i0 = i; }
        }
        // min over lanes of each lane's 3rd-best (safety net)
        float m3 = candv[base + 2];
        #pragma unroll
        for (int L = 1; L < 8; ++L) m3 = fminf(m3, candv[base + L * 3 + 2]);

        // gather candidates within TH of best
        int cl[8]; int cnt = 0;
        #pragma unroll
        for (int t = 0; t < 24; ++t) {
            if (candv[base + t] < v0 + TH_RES) {
                if (cnt < 8) cl[cnt] = candi[base + t];
                ++cnt;
            }
        }

        if (m3 < v0 + TH_RES || cnt > 8) {
            int s = atomicAdd(flagn, 1);
            flags[s] = tid;                      // full chain-fp32 rescan later
            bv_s[tid] = v0; bi_s[tid] = i0;      // placeholder (overwritten)
        } else if (cnt <= 1) {
            bv_s[tid] = v0; bi_s[tid] = i0;
        } else {
            const float* zr = z + (size_t)(row0 + tid) * DDIM;
            float bd = 3.4e38f; int bk = 0x7fffffff;
            for (int t = 0; t < cnt; ++t) {
                int k = cl[t];
                float d = chain_dist_f32(zr, g_Et + (size_t)k * DDIM, en_s[k]);
                if (d < bd || (d == bd && k < bk)) { bd = d; bk = k; }
            }
            bv_s[tid] = bd; bi_s[tid] = bk;
        }
    }
    __syncthreads();

    // ---- rare full chain-fp32 rescan (warp-cooperative) ----
    int nf = *flagn;
    for (int f = wid; f < nf; f += 8) {
        int row = flags[f];
        const float* zr = z + (size_t)(row0 + row) * DDIM;
        float bd = 3.4e38f; int bk = 0x7fffffff;
        for (int k = lane; k < KCODE; k += 32) {
            float d = chain_dist_f32(zr, g_Et + (size_t)k * DDIM, en_s[k]);
            if (d < bd) { bd = d; bk = k; }
        }
        #pragma unroll
        for (int o = 16; o; o >>= 1) {
            float ov = __shfl_xor_sync(0xffffffffu, bd, o);
            int   ok = __shfl_xor_sync(0xffffffffu, bk, o);
            if (ov < bd || (ov == bd && ok < bk)) { bd = ov; bk = ok; }
        }
        if (lane == 0) { bv_s[row] = bd; bi_s[row] = bk; }
    }
    __syncthreads();

    // ---- fused epilogue ----
    float lossacc = 0.f;
    #pragma unroll
    for (int rr = 0; rr < 16; ++rr) {
        int r = wid * 16 + rr;
        int R = row0 + r;
        int k = bi_s[r];
        const float4* zrow = (const float4*)(z + (size_t)R * DDIM);
        float4*       orow = (float4*)(out_zq + (size_t)R * DDIM);
        const float4* et   = (const float4*)(g_Et + (size_t)k * DDIM);
        float zsq = 0.f;
        #pragma unroll
        for (int itc = 0; itc < 2; ++itc) {
            int cidx = lane + itc * 32;
            float4 zv = zrow[cidx];
            zsq += zv.x * zv.x + zv.y * zv.y + zv.z * zv.z + zv.w * zv.w;
            float* es = g_esum + (size_t)k * DDIM + cidx * 4;
            atomicAdd(es + 0, zv.x);
            atomicAdd(es + 1, zv.y);
            atomicAdd(es + 2, zv.z);
            atomicAdd(es + 3, zv.w);
            orow[cidx] = et[cidx];
        }
        #pragma unroll
        for (int o = 16; o; o >>= 1) zsq += __shfl_xor_sync(0xffffffffu, zsq, o);
        if (lane == 0) {
            lossacc += zsq + bv_s[r];
            atomicAdd(&g_counts[k], 1.0f);
        }
    }
    if (lane == 0) atomicAdd(&g_loss, lossacc);
}

// ---------------------------------------------------------------------------
__global__ void k2_stats(const float* __restrict__ cs_in, float* __restrict__ out,
                         long long cs_off, long long loss_off) {
    __shared__ float red[KCODE];
    int t = threadIdx.x;
    float csn = cs_in[t] * DECAY + OMD * g_counts[t];
    out[cs_off + t] = csn;
    red[t] = csn;
    __syncthreads();
    for (int s = 512; s; s >>= 1) {
        if (t < s) red[t] += red[t + s];
        __syncthreads();
    }
    float n  = red[0];
    float cs = (csn + EPSV) / (n + (float)KCODE * EPSV) * n;
    g_invcs[t] = 1.0f / cs;
    if (t == 0) out[loss_off] = VQ_COMMIT * g_loss / (float)((long long)N_TOK * DDIM);
}

__global__ void k3_emb(const float* __restrict__ emean, float* __restrict__ out,
                       long long en_off, long long emn_off) {
    int i = blockIdx.x * blockDim.x + threadIdx.x;
    if (i >= KCODE * DDIM) return;
    int dd = i >> 10;
    int k  = i & 1023;
    float emn = emean[i] * DECAY + OMD * g_esum[(size_t)k * DDIM + dd];
    out[emn_off + i] = emn;
    out[en_off + i]  = emn * g_invcs[k];
}

// ---------------------------------------------------------------------------
extern "C" void kernel_launch(void* const* d_in, const int* in_sizes, int n_in,
                              void* d_out, int out_size) {
    const float* z  = (const float*)d_in[0];
    const float* E  = (const float*)d_in[1];
    const float* cs = (const float*)d_in[2];
    const float* em = (const float*)d_in[3];
    float* out = (float*)d_out;

    long long ND = in_sizes[0];
    long long DK = in_sizes[1];
    long long K  = in_sizes[2];
    long long loss_off = ND;
    long long en_off   = ND + 1;
    long long cs_off   = en_off + DK;
    long long emn_off  = cs_off + K;

    cudaFuncSetAttribute(k1_main, cudaFuncAttributeMaxDynamicSharedMemorySize, SMEM_K1);

    k0_prep<<<512, 256>>>(E);
    k0_enorm<<<128, 256>>>();
    k1_main<<<N_TOK / BM, 256, SMEM_K1>>>(z, out);
    k2_stats<<<1, 1024>>>(cs, out, cs_off, loss_off);
    k3_emb<<<(KCODE * DDIM + 255) / 256, 256>>>(em, out, en_off, emn_off);
}